// round 1
// baseline (speedup 1.0000x reference)
#include <cuda_runtime.h>
#include <math.h>

#define NN 2048
#define AA 100
#define BB 64
#define NTILE 32           // NN / BB
#define OUT_SUM (NN*AA)
#define OUT_G   (NN*AA+1)

// Scratch (static __device__ arrays — no allocation)
__device__ float d_dist[NN*NN];       // 16 MB distance matrix
__device__ int   d_anchors[AA];
__device__ float d_weighted[NN*AA];
__device__ float d_xx[NN];
__device__ float d_rowsum[NN];

__device__ __forceinline__ float finf() { return __int_as_float(0x7f800000); }

// ---------------------------------------------------------------------------
// Build w: adj = motif * nw[i] (row-scaled), w = min(f(adj), f(adj^T)), diag 0
// ---------------------------------------------------------------------------
__global__ void k_build_w(const float* __restrict__ m, const float* __restrict__ nw) {
    int idx = blockIdx.x * 256 + threadIdx.x;
    int i = idx >> 11, j = idx & (NN - 1);
    float a = m[idx] * nw[i];
    float b = m[j * NN + i] * nw[j];
    float wa = a > 0.f ? a : finf();
    float wb = b > 0.f ? b : finf();
    float w = fminf(wa, wb);
    if (i == j) w = 0.f;
    d_dist[idx] = w;
}

// ---------------------------------------------------------------------------
// Blocked Floyd–Warshall, B = 64
// Phase 1: pivot tile (k,k). 256 threads, each owns a 1x16 row segment in regs,
// write-through to shared each step. In-place Gauss–Seidel is the standard
// correct blocked-FW inner update (diag stays 0 so concurrent rewrites are
// value-identical).
// ---------------------------------------------------------------------------
__global__ void __launch_bounds__(256) fw_phase1(int k) {
    __shared__ float t[BB][BB + 4];
    int tid = threadIdx.x;
    int r  = tid >> 2;
    int c0 = (tid & 3) << 4;
    const int base = (k * BB) * NN + k * BB;

    #pragma unroll
    for (int e = tid; e < BB * BB; e += 256)
        t[e >> 6][e & 63] = d_dist[base + (e >> 6) * NN + (e & 63)];
    __syncthreads();

    float cur[16];
    #pragma unroll
    for (int x = 0; x < 16; x++) cur[x] = t[r][c0 + x];

    for (int kk = 0; kk < BB; kk++) {
        float a = t[r][kk];
        float bv[16];
        #pragma unroll
        for (int q = 0; q < 4; q++) {
            float4 v = *(const float4*)&t[kk][c0 + q * 4];
            bv[q*4+0] = v.x; bv[q*4+1] = v.y; bv[q*4+2] = v.z; bv[q*4+3] = v.w;
        }
        #pragma unroll
        for (int x = 0; x < 16; x++)
            cur[x] = fminf(cur[x], a + bv[x]);
        #pragma unroll
        for (int q = 0; q < 4; q++)
            *(float4*)&t[r][c0 + q * 4] =
                make_float4(cur[q*4+0], cur[q*4+1], cur[q*4+2], cur[q*4+3]);
        __syncthreads();
    }
    #pragma unroll
    for (int x = 0; x < 16; x++)
        d_dist[base + r * NN + c0 + x] = cur[x];
}

// ---------------------------------------------------------------------------
// Phase 2: pivot-row tiles (k, o) [y==0] and pivot-col tiles (o, k) [y==1]
// ---------------------------------------------------------------------------
__global__ void __launch_bounds__(256) fw_phase2(int k) {
    int o = blockIdx.x;
    if (o == k) return;
    int tid = threadIdx.x;
    int r  = tid >> 2;
    int c0 = (tid & 3) << 4;
    __shared__ float P[BB][BB + 4];
    __shared__ float C[BB][BB + 4];
    const int pbase = (k * BB) * NN + k * BB;
    const int cbase = (blockIdx.y == 0) ? (k * BB) * NN + o * BB
                                        : (o * BB) * NN + k * BB;
    #pragma unroll
    for (int e = tid; e < BB * BB; e += 256) {
        P[e >> 6][e & 63] = d_dist[pbase + (e >> 6) * NN + (e & 63)];
        C[e >> 6][e & 63] = d_dist[cbase + (e >> 6) * NN + (e & 63)];
    }
    __syncthreads();

    float cur[16];
    #pragma unroll
    for (int x = 0; x < 16; x++) cur[x] = C[r][c0 + x];

    if (blockIdx.y == 0) {
        // C[r][c] = min(C[r][c], P[r][kk] + C[kk][c])
        for (int kk = 0; kk < BB; kk++) {
            float a = P[r][kk];
            float bv[16];
            #pragma unroll
            for (int q = 0; q < 4; q++) {
                float4 v = *(const float4*)&C[kk][c0 + q * 4];
                bv[q*4+0] = v.x; bv[q*4+1] = v.y; bv[q*4+2] = v.z; bv[q*4+3] = v.w;
            }
            #pragma unroll
            for (int x = 0; x < 16; x++)
                cur[x] = fminf(cur[x], a + bv[x]);
            #pragma unroll
            for (int q = 0; q < 4; q++)
                *(float4*)&C[r][c0 + q * 4] =
                    make_float4(cur[q*4+0], cur[q*4+1], cur[q*4+2], cur[q*4+3]);
            __syncthreads();
        }
    } else {
        // C[r][c] = min(C[r][c], C[r][kk] + P[kk][c])
        for (int kk = 0; kk < BB; kk++) {
            float a = C[r][kk];
            float bv[16];
            #pragma unroll
            for (int q = 0; q < 4; q++) {
                float4 v = *(const float4*)&P[kk][c0 + q * 4];
                bv[q*4+0] = v.x; bv[q*4+1] = v.y; bv[q*4+2] = v.z; bv[q*4+3] = v.w;
            }
            #pragma unroll
            for (int x = 0; x < 16; x++)
                cur[x] = fminf(cur[x], a + bv[x]);
            #pragma unroll
            for (int q = 0; q < 4; q++)
                *(float4*)&C[r][c0 + q * 4] =
                    make_float4(cur[q*4+0], cur[q*4+1], cur[q*4+2], cur[q*4+3]);
            __syncthreads();
        }
    }
    #pragma unroll
    for (int x = 0; x < 16; x++)
        d_dist[cbase + r * NN + c0 + x] = cur[x];
}

// ---------------------------------------------------------------------------
// Phase 3: C(by,bx) = min(C, A(by,k) (+,min)x B(k,bx)). Register-tiled 4x4
// micro, min-plus GEMM. This is the hot kernel (issue-bound on FADD+FMNMX).
// ---------------------------------------------------------------------------
__global__ void __launch_bounds__(256) fw_phase3(int k) {
    int bx = blockIdx.x, by = blockIdx.y;
    if (bx == k || by == k) return;
    __shared__ float AsT[BB][BB + 4];   // AsT[kk][r]
    __shared__ float Bs [BB][BB + 4];   // Bs[kk][c]
    int tid = threadIdx.x;
    const int abase = (by * BB) * NN + k * BB;
    const int bbase = (k * BB) * NN + bx * BB;
    #pragma unroll
    for (int e = tid; e < BB * BB; e += 256) {
        int rr = e >> 6, cc = e & 63;
        AsT[cc][rr] = d_dist[abase + rr * NN + cc];
        Bs [rr][cc] = d_dist[bbase + rr * NN + cc];
    }
    int tx = tid & 15, ty = tid >> 4;
    int r0 = ty << 2, c0 = tx << 2;
    const int cbase = (by * BB + r0) * NN + bx * BB + c0;
    float acc[4][4];
    #pragma unroll
    for (int a = 0; a < 4; a++) {
        float4 v = *(const float4*)&d_dist[cbase + a * NN];
        acc[a][0] = v.x; acc[a][1] = v.y; acc[a][2] = v.z; acc[a][3] = v.w;
    }
    __syncthreads();
    #pragma unroll 8
    for (int kk = 0; kk < BB; kk++) {
        float4 a4 = *(const float4*)&AsT[kk][r0];
        float4 b4 = *(const float4*)&Bs[kk][c0];
        float av[4] = {a4.x, a4.y, a4.z, a4.w};
        float bv[4] = {b4.x, b4.y, b4.z, b4.w};
        #pragma unroll
        for (int a = 0; a < 4; a++)
            #pragma unroll
            for (int b = 0; b < 4; b++)
                acc[a][b] = fminf(acc[a][b], av[a] + bv[b]);
    }
    #pragma unroll
    for (int a = 0; a < 4; a++)
        *(float4*)&d_dist[cbase + a * NN] =
            make_float4(acc[a][0], acc[a][1], acc[a][2], acc[a][3]);
}

// ---------------------------------------------------------------------------
// Anchors: exact stable argsort(-nw)[:100] via rank counting
// rank_i = #{j: nw_j > nw_i} + #{j<i: nw_j == nw_i}
// ---------------------------------------------------------------------------
__global__ void k_anchors(const float* __restrict__ nw) {
    __shared__ float s[NN];
    int tid = threadIdx.x;
    for (int e = tid; e < NN; e += 256) s[e] = nw[e];
    __syncthreads();
    int i = blockIdx.x * 256 + tid;
    float v = s[i];
    int rank = 0;
    for (int j = 0; j < NN; j++) {
        float u = s[j];
        rank += (u > v) || (u == v && j < i);
    }
    if (rank < AA) d_anchors[rank] = i;
}

// ---------------------------------------------------------------------------
// Gather consensus vectors (inf->100), weighted = wm*cv, per-row sums
// (deterministic tree reductions — no fp atomics)
// ---------------------------------------------------------------------------
__global__ void k_gather(const float* __restrict__ wm, float* __restrict__ out) {
    __shared__ int anc[AA];
    __shared__ float r1[128], r2[128];
    int i = blockIdx.x, tid = threadIdx.x;
    if (tid < AA) anc[tid] = d_anchors[tid];
    __syncthreads();
    float cv = 0.f, wsq = 0.f;
    if (tid < AA) {
        float v = d_dist[i * NN + anc[tid]];
        if (v > 3.0e38f) v = 100.f;           // isinf -> 100
        out[i * AA + tid] = v;
        float w = wm[i * AA + tid] * v;
        d_weighted[i * AA + tid] = w;
        cv = v; wsq = w * w;
    }
    r1[tid] = cv; r2[tid] = wsq;
    __syncthreads();
    for (int st = 64; st > 0; st >>= 1) {
        if (tid < st) { r1[tid] += r1[tid + st]; r2[tid] += r2[tid + st]; }
        __syncthreads();
    }
    if (tid == 0) { d_rowsum[i] = r1[0]; d_xx[i] = r2[0]; }
}

__global__ void k_finalize(float* __restrict__ out) {
    __shared__ float red[256];
    int tid = threadIdx.x;
    float s = 0.f;
    for (int e = tid; e < NN; e += 256) s += d_rowsum[e];
    red[tid] = s;
    __syncthreads();
    for (int st = 128; st > 0; st >>= 1) {
        if (tid < st) red[tid] += red[tid + st];
        __syncthreads();
    }
    if (tid == 0) out[OUT_SUM] = (red[0] - 100.f * NN) / ((float)NN * AA);
}

// ---------------------------------------------------------------------------
// Consensus graph: sq = max(xx_i + xx_j - 2*dot, 0); out = exp(-sq^2/(2 s^2))
// K=100 FMA GEMM, 64x64 tiles, 4x4 micro
// ---------------------------------------------------------------------------
__global__ void __launch_bounds__(256) k_graph(const float* __restrict__ sigma_p,
                                               float* __restrict__ out) {
    __shared__ float WiT[32][BB + 4];
    __shared__ float WjT[32][BB + 4];
    int bx = blockIdx.x, by = blockIdx.y;
    int tid = threadIdx.x, tx = tid & 15, ty = tid >> 4;
    int r0 = ty << 2, c0 = tx << 2;
    float acc[4][4] = {};
    for (int k0 = 0; k0 < 128; k0 += 32) {
        for (int e = tid; e < BB * 32; e += 256) {
            int rr = e >> 5, kc = e & 31;
            int kg = k0 + kc;
            float wi = 0.f, wj = 0.f;
            if (kg < AA) {
                wi = d_weighted[(by * BB + rr) * AA + kg];
                wj = d_weighted[(bx * BB + rr) * AA + kg];
            }
            WiT[kc][rr] = wi; WjT[kc][rr] = wj;
        }
        __syncthreads();
        #pragma unroll
        for (int kc = 0; kc < 32; kc++) {
            float4 a4 = *(const float4*)&WiT[kc][r0];
            float4 b4 = *(const float4*)&WjT[kc][c0];
            float av[4] = {a4.x, a4.y, a4.z, a4.w};
            float bv[4] = {b4.x, b4.y, b4.z, b4.w};
            #pragma unroll
            for (int a = 0; a < 4; a++)
                #pragma unroll
                for (int b = 0; b < 4; b++)
                    acc[a][b] += av[a] * bv[b];
        }
        __syncthreads();
    }
    float sg = *sigma_p;
    float inv2 = 0.5f / (sg * sg);
    float xi[4], xj[4];
    #pragma unroll
    for (int a = 0; a < 4; a++) xi[a] = d_xx[by * BB + r0 + a];
    #pragma unroll
    for (int b = 0; b < 4; b++) xj[b] = d_xx[bx * BB + c0 + b];
    #pragma unroll
    for (int a = 0; a < 4; a++) {
        int i = by * BB + r0 + a;
        #pragma unroll
        for (int b = 0; b < 4; b++) {
            int j = bx * BB + c0 + b;
            float sq = xi[a] + xj[b] - 2.f * acc[a][b];
            sq = fmaxf(sq, 0.f);
            out[OUT_G + i * NN + j] = expf(-(sq * sq) * inv2);
        }
    }
}

// ---------------------------------------------------------------------------
extern "C" void kernel_launch(void* const* d_in, const int* in_sizes, int n_in,
                              void* d_out, int out_size) {
    const float* m  = (const float*)d_in[0];   // motifGraph (2048*2048)
    const float* nw = (const float*)d_in[1];   // node_weights (2048)
    const float* wm = (const float*)d_in[2];   // weight_matrix (2048*100)
    const float* sg = (const float*)d_in[3];   // sigma (1)
    float* out = (float*)d_out;

    k_build_w<<<(NN * NN) / 256, 256>>>(m, nw);
    for (int k = 0; k < NTILE; k++) {
        fw_phase1<<<1, 256>>>(k);
        fw_phase2<<<dim3(NTILE, 2), 256>>>(k);
        fw_phase3<<<dim3(NTILE, NTILE), 256>>>(k);
    }
    k_anchors<<<NN / 256, 256>>>(nw);
    k_gather<<<NN, 128>>>(wm, out);
    k_finalize<<<1, 256>>>(out);
    k_graph<<<dim3(NTILE, NTILE), 256>>>(sg, out);
}

// round 4
// speedup vs baseline: 1.3481x; 1.3481x over previous
#include <cuda_runtime.h>
#include <math.h>

#define NN 2048
#define AA 100
#define BB 64
#define NTILE 32           // NN / BB (FW block grid)
#define OUT_SUM (NN*AA)
#define OUT_G   (NN*AA+1)

// Scratch (static __device__ arrays — no allocation)
__device__ float d_dist[NN*NN];       // 16 MB distance matrix
__device__ int   d_anchors[AA];
__device__ float d_weighted[NN*AA];
__device__ float d_xx[NN];
__device__ float d_rowsum[NN];

__device__ __forceinline__ float finf() { return __int_as_float(0x7f800000); }

// ---------------------------------------------------------------------------
// Build w: adj = motif * nw[i] (row-scaled), w = min(f(adj), f(adj^T)), diag 0
// Tiled so both the direct and transposed reads are coalesced.
// ---------------------------------------------------------------------------
__global__ void __launch_bounds__(256) k_build_w(const float* __restrict__ m,
                                                 const float* __restrict__ nw) {
    __shared__ float sT[32][33];     // sT[rr][cc] = m[(bj*32+rr)][bi*32+cc]
    int bi = blockIdx.y, bj = blockIdx.x;
    int tx = threadIdx.x & 31;
    int ty = threadIdx.x >> 5;       // 0..7
    #pragma unroll
    for (int rr = ty; rr < 32; rr += 8)
        sT[rr][tx] = m[(bj*32 + rr)*NN + bi*32 + tx];
    __syncthreads();
    #pragma unroll
    for (int rr = ty; rr < 32; rr += 8) {
        int i = bi*32 + rr;
        int j = bj*32 + tx;
        float a = m[i*NN + j] * nw[i];
        float b = sT[tx][rr] * nw[j];     // m[j][i] * nw[j]
        float wa = a > 0.f ? a : finf();
        float wb = b > 0.f ? b : finf();
        float w = fminf(wa, wb);
        if (i == j) w = 0.f;
        d_dist[i*NN + j] = w;
    }
}

// ---------------------------------------------------------------------------
// Fused phase1+2. Grid = 64 blocks.
//   All blocks: load pivot tile (k,k), compute its transitive closure P*
//   (sequential Gauss-Seidel in smem, redundant per block).
//   bid in [0,32):  row tile (k,o):  C_new = P* (min,+) C_old   (pure GEMM)
//   bid in [32,64): col tile (o,k):  C_new = C_old (min,+) P*
//   o spans ALL 32 tiles incl. the pivot tile: updates there are idempotent
//   (diag(P*)=0 supplies the zero-hop term), and P/P* read mixtures are safe.
// ---------------------------------------------------------------------------
__global__ void __launch_bounds__(256) fw_p12(int k) {
    __shared__ float Ps[BB][BB + 4];   // pivot (then row-branch: C slab)
    __shared__ float B1[BB][BB + 4];   // row-branch: P*^T ; col-branch: C^T
    int tid = threadIdx.x;
    const int kB = k * BB;
    const int pbase = kB * NN + kB;

    #pragma unroll
    for (int e = tid; e < BB * BB; e += 256)
        Ps[e >> 6][e & 63] = d_dist[pbase + (e >> 6) * NN + (e & 63)];
    __syncthreads();

    // ---- closure of pivot tile (write-through Gauss-Seidel) ----
    int r  = tid >> 2;
    int c0 = (tid & 3) << 4;
    float cur[16];
    #pragma unroll
    for (int x = 0; x < 16; x++) cur[x] = Ps[r][c0 + x];

    for (int kk = 0; kk < BB; kk++) {
        float a = Ps[r][kk];
        float bv[16];
        #pragma unroll
        for (int q = 0; q < 4; q++) {
            float4 v = *(const float4*)&Ps[kk][c0 + q * 4];
            bv[q*4+0] = v.x; bv[q*4+1] = v.y; bv[q*4+2] = v.z; bv[q*4+3] = v.w;
        }
        #pragma unroll
        for (int x = 0; x < 16; x++)
            cur[x] = fminf(cur[x], a + bv[x]);
        #pragma unroll
        for (int q = 0; q < 4; q++)
            *(float4*)&Ps[r][c0 + q * 4] =
                make_float4(cur[q*4+0], cur[q*4+1], cur[q*4+2], cur[q*4+3]);
        __syncthreads();
    }
    // Ps now holds P*; cur holds this thread's 1x16 segment of P*.

    int bid = blockIdx.x;
    int o = bid & 31;
    int tx = tid & 15, ty = tid >> 4;
    int rr0 = ty << 2, cc0 = tx << 2;
    float acc[4][4];
    #pragma unroll
    for (int a = 0; a < 4; a++)
        #pragma unroll
        for (int b = 0; b < 4; b++) acc[a][b] = finf();

    if (bid < 32) {
        // row tile (k, o): need P*^T and C slab.
        #pragma unroll
        for (int x = 0; x < 16; x++) B1[c0 + x][r] = cur[x];   // P*^T
        #pragma unroll
        for (int e = tid; e < BB * BB; e += 256)
            Ps[e >> 6][e & 63] = d_dist[(kB + (e >> 6)) * NN + o * BB + (e & 63)];
        __syncthreads();
        #pragma unroll 4
        for (int p = 0; p < BB; p++) {
            float4 a4 = *(const float4*)&B1[p][rr0];   // P*[i][p], i=rr0..+3
            float4 b4 = *(const float4*)&Ps[p][cc0];   // C_old[p][j]
            float av[4] = {a4.x, a4.y, a4.z, a4.w};
            float bv[4] = {b4.x, b4.y, b4.z, b4.w};
            #pragma unroll
            for (int a = 0; a < 4; a++)
                #pragma unroll
                for (int b = 0; b < 4; b++)
                    acc[a][b] = fminf(acc[a][b], av[a] + bv[b]);
        }
        #pragma unroll
        for (int a = 0; a < 4; a++)
            *(float4*)&d_dist[(kB + rr0 + a) * NN + o * BB + cc0] =
                make_float4(acc[a][0], acc[a][1], acc[a][2], acc[a][3]);
    } else {
        // col tile (o, k): need C^T slab; keep Ps = P*.
        #pragma unroll
        for (int e = tid; e < BB * BB; e += 256) {
            int ii = e >> 6, p = e & 63;
            B1[p][ii] = d_dist[(o * BB + ii) * NN + kB + p];
        }
        __syncthreads();
        #pragma unroll 4
        for (int p = 0; p < BB; p++) {
            float4 a4 = *(const float4*)&B1[p][rr0];   // C_old[i][p]
            float4 b4 = *(const float4*)&Ps[p][cc0];   // P*[p][j]
            float av[4] = {a4.x, a4.y, a4.z, a4.w};
            float bv[4] = {b4.x, b4.y, b4.z, b4.w};
            #pragma unroll
            for (int a = 0; a < 4; a++)
                #pragma unroll
                for (int b = 0; b < 4; b++)
                    acc[a][b] = fminf(acc[a][b], av[a] + bv[b]);
        }
        #pragma unroll
        for (int a = 0; a < 4; a++)
            *(float4*)&d_dist[(o * BB + rr0 + a) * NN + kB + cc0] =
                make_float4(acc[a][0], acc[a][1], acc[a][2], acc[a][3]);
    }
}

// ---------------------------------------------------------------------------
// Phase 3: 128x128 C tiles, K = 64 panel, 8x8 microtile per thread.
// C(by,bx) = min(C, A(:,k) (+,min)x B(k,:)). Uniform grid (pivot panels are
// idempotent). Dynamic smem: AsT[64][132] + Bs[64][128].
// ---------------------------------------------------------------------------
#define ASTR 132
__global__ void __launch_bounds__(256, 2) fw_phase3(int k) {
    extern __shared__ float sm[];
    float* AsT = sm;                    // [64][ASTR]  AsT[p][i]
    float* Bs  = sm + BB * ASTR;        // [64][128]   Bs[p][j]
    int tid = threadIdx.x;
    int bx = blockIdx.x, by = blockIdx.y;
    const int kB = k * BB;

    // A: 128 rows x 64 cols, stored transposed
    #pragma unroll
    for (int e = tid; e < 128 * 64; e += 256) {
        int rr = e >> 6, p = e & 63;
        AsT[p * ASTR + rr] = d_dist[(by * 128 + rr) * NN + kB + p];
    }
    // B: 64 rows x 128 cols
    #pragma unroll
    for (int e = tid; e < 64 * 128; e += 256) {
        int p = e >> 7, j = e & 127;
        Bs[p * 128 + j] = d_dist[(kB + p) * NN + bx * 128 + j];
    }

    int tx = tid & 15, ty = tid >> 4;
    int r0 = ty << 3, c0 = tx << 3;
    const int cbase = (by * 128 + r0) * NN + bx * 128 + c0;
    float acc[8][8];
    #pragma unroll
    for (int a = 0; a < 8; a++) {
        float4 v0 = *(const float4*)&d_dist[cbase + a * NN];
        float4 v1 = *(const float4*)&d_dist[cbase + a * NN + 4];
        acc[a][0] = v0.x; acc[a][1] = v0.y; acc[a][2] = v0.z; acc[a][3] = v0.w;
        acc[a][4] = v1.x; acc[a][5] = v1.y; acc[a][6] = v1.z; acc[a][7] = v1.w;
    }
    __syncthreads();

    #pragma unroll 4
    for (int p = 0; p < BB; p++) {
        float4 a0 = *(const float4*)&AsT[p * ASTR + r0];
        float4 a1 = *(const float4*)&AsT[p * ASTR + r0 + 4];
        float4 b0 = *(const float4*)&Bs[p * 128 + c0];
        float4 b1 = *(const float4*)&Bs[p * 128 + c0 + 4];
        float av[8] = {a0.x, a0.y, a0.z, a0.w, a1.x, a1.y, a1.z, a1.w};
        float bv[8] = {b0.x, b0.y, b0.z, b0.w, b1.x, b1.y, b1.z, b1.w};
        #pragma unroll
        for (int a = 0; a < 8; a++)
            #pragma unroll
            for (int b = 0; b < 8; b++)
                acc[a][b] = fminf(acc[a][b], av[a] + bv[b]);
    }

    #pragma unroll
    for (int a = 0; a < 8; a++) {
        *(float4*)&d_dist[cbase + a * NN] =
            make_float4(acc[a][0], acc[a][1], acc[a][2], acc[a][3]);
        *(float4*)&d_dist[cbase + a * NN + 4] =
            make_float4(acc[a][4], acc[a][5], acc[a][6], acc[a][7]);
    }
}

// ---------------------------------------------------------------------------
// Anchors: exact stable argsort(-nw)[:100] via rank counting
// ---------------------------------------------------------------------------
__global__ void k_anchors(const float* __restrict__ nw) {
    __shared__ float s[NN];
    int tid = threadIdx.x;
    for (int e = tid; e < NN; e += 256) s[e] = nw[e];
    __syncthreads();
    int i = blockIdx.x * 256 + tid;
    float v = s[i];
    int rank = 0;
    for (int j = 0; j < NN; j++) {
        float u = s[j];
        rank += (u > v) || (u == v && j < i);
    }
    if (rank < AA) d_anchors[rank] = i;
}

// ---------------------------------------------------------------------------
// Gather consensus vectors (inf->100), weighted = wm*cv, per-row sums
// ---------------------------------------------------------------------------
__global__ void k_gather(const float* __restrict__ wm, float* __restrict__ out) {
    __shared__ int anc[AA];
    __shared__ float r1[128], r2[128];
    int i = blockIdx.x, tid = threadIdx.x;
    if (tid < AA) anc[tid] = d_anchors[tid];
    __syncthreads();
    float cv = 0.f, wsq = 0.f;
    if (tid < AA) {
        float v = d_dist[i * NN + anc[tid]];
        if (v > 3.0e38f) v = 100.f;
        out[i * AA + tid] = v;
        float w = wm[i * AA + tid] * v;
        d_weighted[i * AA + tid] = w;
        cv = v; wsq = w * w;
    }
    r1[tid] = cv; r2[tid] = wsq;
    __syncthreads();
    for (int st = 64; st > 0; st >>= 1) {
        if (tid < st) { r1[tid] += r1[tid + st]; r2[tid] += r2[tid + st]; }
        __syncthreads();
    }
    if (tid == 0) { d_rowsum[i] = r1[0]; d_xx[i] = r2[0]; }
}

__global__ void k_finalize(float* __restrict__ out) {
    __shared__ float red[256];
    int tid = threadIdx.x;
    float s = 0.f;
    for (int e = tid; e < NN; e += 256) s += d_rowsum[e];
    red[tid] = s;
    __syncthreads();
    for (int st = 128; st > 0; st >>= 1) {
        if (tid < st) red[tid] += red[tid + st];
        __syncthreads();
    }
    if (tid == 0) out[OUT_SUM] = (red[0] - 100.f * NN) / ((float)NN * AA);
}

// ---------------------------------------------------------------------------
// Consensus graph: sq = max(xx_i + xx_j - 2*dot, 0); out = exp(-sq^2/(2 s^2))
// ---------------------------------------------------------------------------
__global__ void __launch_bounds__(256) k_graph(const float* __restrict__ sigma_p,
                                               float* __restrict__ out) {
    __shared__ float WiT[32][BB + 4];
    __shared__ float WjT[32][BB + 4];
    int bx = blockIdx.x, by = blockIdx.y;
    int tid = threadIdx.x, tx = tid & 15, ty = tid >> 4;
    int r0 = ty << 2, c0 = tx << 2;
    float acc[4][4] = {};
    for (int k0 = 0; k0 < 128; k0 += 32) {
        for (int e = tid; e < BB * 32; e += 256) {
            int rr = e >> 5, kc = e & 31;
            int kg = k0 + kc;
            float wi = 0.f, wj = 0.f;
            if (kg < AA) {
                wi = d_weighted[(by * BB + rr) * AA + kg];
                wj = d_weighted[(bx * BB + rr) * AA + kg];
            }
            WiT[kc][rr] = wi; WjT[kc][rr] = wj;
        }
        __syncthreads();
        #pragma unroll
        for (int kc = 0; kc < 32; kc++) {
            float4 a4 = *(const float4*)&WiT[kc][r0];
            float4 b4 = *(const float4*)&WjT[kc][c0];
            float av[4] = {a4.x, a4.y, a4.z, a4.w};
            float bv[4] = {b4.x, b4.y, b4.z, b4.w};
            #pragma unroll
            for (int a = 0; a < 4; a++)
                #pragma unroll
                for (int b = 0; b < 4; b++)
                    acc[a][b] += av[a] * bv[b];
        }
        __syncthreads();
    }
    float sg = *sigma_p;
    float inv2 = 0.5f / (sg * sg);
    float xi[4], xj[4];
    #pragma unroll
    for (int a = 0; a < 4; a++) xi[a] = d_xx[by * BB + r0 + a];
    #pragma unroll
    for (int b = 0; b < 4; b++) xj[b] = d_xx[bx * BB + c0 + b];
    #pragma unroll
    for (int a = 0; a < 4; a++) {
        int i = by * BB + r0 + a;
        #pragma unroll
        for (int b = 0; b < 4; b++) {
            int j = bx * BB + c0 + b;
            float sq = xi[a] + xj[b] - 2.f * acc[a][b];
            sq = fmaxf(sq, 0.f);
            out[OUT_G + i * NN + j] = expf(-(sq * sq) * inv2);
        }
    }
}

// ---------------------------------------------------------------------------
extern "C" void kernel_launch(void* const* d_in, const int* in_sizes, int n_in,
                              void* d_out, int out_size) {
    const float* m  = (const float*)d_in[0];   // motifGraph (2048*2048)
    const float* nw = (const float*)d_in[1];   // node_weights (2048)
    const float* wm = (const float*)d_in[2];   // weight_matrix (2048*100)
    const float* sg = (const float*)d_in[3];   // sigma (1)
    float* out = (float*)d_out;

    const int p3_smem = (BB * ASTR + BB * 128) * (int)sizeof(float);  // 66560 B
    cudaFuncSetAttribute(fw_phase3, cudaFuncAttributeMaxDynamicSharedMemorySize,
                         p3_smem);

    k_build_w<<<dim3(NN/32, NN/32), 256>>>(m, nw);
    k_anchors<<<NN / 256, 256>>>(nw);          // independent of FW
    for (int k = 0; k < NTILE; k++) {
        fw_p12<<<64, 256>>>(k);
        fw_phase3<<<dim3(16, 16), 256, p3_smem>>>(k);
    }
    k_gather<<<NN, 128>>>(wm, out);
    k_finalize<<<1, 256>>>(out);
    k_graph<<<dim3(NTILE, NTILE), 256>>>(sg, out);
}